// round 4
// baseline (speedup 1.0000x reference)
#include <cuda_runtime.h>
#include <cstdint>

#define HAT_EPS   1e-5f
#define ALPHA_CAP 2000000
#define FULLMASK  0xffffffffu

// accumulators: [0]=sum softplus(pos), [1]=sum softplus(-neg), [2]=sum 1/(rank+1)
static __device__ double g_acc[3];          // zero-initialized at module load
static __device__ unsigned int g_done;      // ticket counter, reset by last block
static __device__ float g_ia[ALPHA_CAP];    // 1/max(1-||h_i||^2, eps)

__device__ __forceinline__ float hat_softplus(float x) {
    if (x > 30.0f) return x;
    return __logf(1.0f + __expf(x));
}

// ---------------------------------------------------------------------------
// Prepass: g_ia[i] = 1 / max(1 - ||h_i||^2, eps).  D=64, 16 lanes per node.
// ---------------------------------------------------------------------------
__global__ void __launch_bounds__(256) hat_alpha_kernel(const float* __restrict__ h, int N) {
    int tid  = blockIdx.x * blockDim.x + threadIdx.x;
    int node = tid >> 4;
    int sub  = tid & 15;
    if (node >= N) return;
    float4 a = __ldg((const float4*)(h + (size_t)node * 64) + sub);
    float s = fmaf(a.x, a.x, fmaf(a.y, a.y, fmaf(a.z, a.z, a.w * a.w)));
    s += __shfl_xor_sync(FULLMASK, s, 8);
    s += __shfl_xor_sync(FULLMASK, s, 4);
    s += __shfl_xor_sync(FULLMASK, s, 2);
    s += __shfl_xor_sync(FULLMASK, s, 1);
    if (sub == 0) g_ia[node] = 1.0f / fmaxf(1.0f - s, HAT_EPS);
}

// ---------------------------------------------------------------------------
// Main fused kernel, NN=5: one warp per positive group (pos + 5 negs).
// Half-warps (16 lanes, float4/lane) gather+reduce sq for distances
// t = half, half+2, half+4. Then all 6 scores are computed IN PARALLEL on
// lanes 0..5 (one transcendental pass per warp instead of six).
// ---------------------------------------------------------------------------
__global__ void __launch_bounds__(256) hat_fused5_kernel(
    const float* __restrict__ h,
    const int* __restrict__ ps, const int* __restrict__ pd,
    const int* __restrict__ ns, const int* __restrict__ nd,
    int E_pos, int E_neg, float* __restrict__ out, int out_size)
{
    const int lane = threadIdx.x & 31;
    const int wid  = threadIdx.x >> 5;
    const int g    = blockIdx.x * (blockDim.x >> 5) + wid;
    const int half = lane >> 4;
    const int sub  = lane & 15;

    float sp_pos = 0.0f, sp_neg = 0.0f, inv_rank = 0.0f;

    if (g < E_pos) {
        // ---- lanes 0-5 load src indices, lanes 8-13 load dst indices ----
        int idx = 0;
        if (lane == 0)                      idx = __ldg(&ps[g]);
        else if (lane <= 5)                 idx = __ldg(&ns[g * 5 + (lane - 1)]);
        else if (lane == 8)                 idx = __ldg(&pd[g]);
        else if (lane >= 9 && lane <= 13)   idx = __ldg(&nd[g * 5 + (lane - 9)]);
        // same lanes gather inv_alpha in parallel (2MB array, L2-resident)
        float ia = 0.0f;
        if ((lane <= 5) || (lane >= 8 && lane <= 13)) ia = __ldg(&g_ia[idx]);

        // ---- batch all 6 row-pair loads (deep MLP hides L2 latency) ----
        float4 a[3], b[3];
        #pragma unroll
        for (int k = 0; k < 3; k++) {
            const int t = half + 2 * k;               // 0..5
            int src = __shfl_sync(FULLMASK, idx, t);
            int dst = __shfl_sync(FULLMASK, idx, 8 + t);
            a[k] = __ldg((const float4*)(h + (size_t)src * 64) + sub);
            b[k] = __ldg((const float4*)(h + (size_t)dst * 64) + sub);
        }

        // ---- per-half ||u-v||^2 reductions (the ONLY butterfly chains) ----
        float sq[3];
        #pragma unroll
        for (int k = 0; k < 3; k++) {
            float dx = a[k].x - b[k].x, dy = a[k].y - b[k].y;
            float dz = a[k].z - b[k].z, dw = a[k].w - b[k].w;
            float s = fmaf(dx, dx, fmaf(dy, dy, fmaf(dz, dz, dw * dw)));
            s += __shfl_xor_sync(FULLMASK, s, 8);
            s += __shfl_xor_sync(FULLMASK, s, 4);
            s += __shfl_xor_sync(FULLMASK, s, 2);
            s += __shfl_xor_sync(FULLMASK, s, 1);
            sq[k] = s;   // uniform within each half
        }

        // ---- route distance t's sq to lane t (t = 0..5) ----
        float o0 = __shfl_xor_sync(FULLMASK, sq[0], 16);   // other half's values
        float o1 = __shfl_xor_sync(FULLMASK, sq[1], 16);
        float o2 = __shfl_xor_sync(FULLMASK, sq[2], 16);
        // lanes 0..5 are in half 0: even t -> own sq[t/2], odd t -> o[(t-1)/2]
        float ev = (lane >= 4) ? sq[2] : ((lane >= 2) ? sq[1] : sq[0]);
        float od = (lane >= 4) ? o2    : ((lane >= 2) ? o1    : o0);
        float sv = (lane & 1) ? od : ev;

        // inv_alpha product: lane t has its own src ia; dst ia lives at lane t+8
        float ib = __shfl_sync(FULLMASK, ia, (lane & 7) + 8);
        float pr = ia * ib;

        // ---- ONE score + softplus pass covers all 6 distances ----
        float gam = fmaxf(fmaf(2.0f * sv, pr, 1.0f), 1.0f + HAT_EPS);
        float d   = __logf(gam + __fsqrt_rn(fmaf(gam, gam, -1.0f)));
        float scv = d * d;

        float pos = __shfl_sync(FULLMASK, scv, 0);
        unsigned ball = __ballot_sync(FULLMASK, scv < pos);   // -ns > -ps <=> ns < ps
        int cnt = __popc(ball & 0x3Eu);                       // lanes 1..5

        float arg = (lane == 0) ? scv : -scv;
        float sp  = hat_softplus(arg);
        float vneg = (lane >= 1 && lane <= 5) ? sp : 0.0f;
        vneg += __shfl_xor_sync(FULLMASK, vneg, 4);
        vneg += __shfl_xor_sync(FULLMASK, vneg, 2);
        vneg += __shfl_xor_sync(FULLMASK, vneg, 1);

        if (lane == 0) {
            sp_pos   = sp;
            sp_neg   = vneg;
            inv_rank = 1.0f / (float)(cnt + 1);
        }
    }

    // ---- block reduction -> global double atomics ----
    __shared__ float s_a[8], s_b[8], s_c[8];
    __shared__ bool  s_last;
    if (lane == 0) { s_a[wid] = sp_pos; s_b[wid] = sp_neg; s_c[wid] = inv_rank; }
    __syncthreads();
    if (wid == 0) {
        const int nw = blockDim.x >> 5;
        float va = (lane < nw) ? s_a[lane] : 0.0f;
        float vb = (lane < nw) ? s_b[lane] : 0.0f;
        float vc = (lane < nw) ? s_c[lane] : 0.0f;
        #pragma unroll
        for (int off = 4; off >= 1; off >>= 1) {
            va += __shfl_xor_sync(FULLMASK, va, off);
            vb += __shfl_xor_sync(FULLMASK, vb, off);
            vc += __shfl_xor_sync(FULLMASK, vc, off);
        }
        if (lane == 0) {
            atomicAdd(&g_acc[0], (double)va);
            atomicAdd(&g_acc[1], (double)vb);
            atomicAdd(&g_acc[2], (double)vc);
            __threadfence();
            unsigned ticket = atomicAdd(&g_done, 1u);
            s_last = (ticket == gridDim.x - 1);
        }
    }
    __syncthreads();

    // ---- last block finalizes and resets state for the next graph replay ----
    if (s_last && threadIdx.x == 0) {
        volatile double* acc = (volatile double*)g_acc;
        double a = acc[0], b = acc[1], c = acc[2];
        out[0] = (float)(a / (double)E_pos + b / (double)E_neg);
        if (out_size > 1) out[1] = (float)(c / (double)E_pos);
        g_acc[0] = 0.0; g_acc[1] = 0.0; g_acc[2] = 0.0;
        g_done = 0u;
        __threadfence();
    }
}

// ---------------------------------------------------------------------------
// Generic fallback (any nn), self-contained: init, compute, fin.
// ---------------------------------------------------------------------------
__global__ void hat_init_kernel() {
    g_acc[0] = 0.0; g_acc[1] = 0.0; g_acc[2] = 0.0;
}

__global__ void __launch_bounds__(256) hat_generic_kernel(
    const float* __restrict__ h,
    const int* __restrict__ ps, const int* __restrict__ pd,
    const int* __restrict__ ns, const int* __restrict__ nd,
    int E_pos, int nn)
{
    const int lane = threadIdx.x & 31;
    const int wid  = threadIdx.x >> 5;
    const int g    = blockIdx.x * (blockDim.x >> 5) + wid;

    float sp_pos = 0.0f, sp_neg = 0.0f, inv_rank = 0.0f;

    if (g < E_pos) {
        float pos = 0.0f;
        int   cnt = 0;
        for (int t = 0; t <= nn; t++) {
            int src, dst;
            if (t == 0) { src = ps[g]; dst = pd[g]; }
            else {
                size_t e = (size_t)g * nn + (t - 1);
                src = ns[e]; dst = nd[e];
            }
            const float2* up = (const float2*)(h + (size_t)src * 64);
            const float2* vp = (const float2*)(h + (size_t)dst * 64);
            float2 a = up[lane], b = vp[lane];
            float dx = a.x - b.x, dy = a.y - b.y;
            float sq = dx * dx + dy * dy;
            float uu = a.x * a.x + a.y * a.y;
            float vv = b.x * b.x + b.y * b.y;
            #pragma unroll
            for (int off = 16; off >= 1; off >>= 1) {
                sq += __shfl_xor_sync(FULLMASK, sq, off);
                uu += __shfl_xor_sync(FULLMASK, uu, off);
                vv += __shfl_xor_sync(FULLMASK, vv, off);
            }
            if (lane == 0) {
                float alpha = fmaxf(1.0f - uu, HAT_EPS);
                float beta  = fmaxf(1.0f - vv, HAT_EPS);
                float gam   = fmaxf(1.0f + 2.0f * sq / (alpha * beta), 1.0f + HAT_EPS);
                float dd    = __logf(gam + __fsqrt_rn(fmaf(gam, gam, -1.0f)));
                float scv   = dd * dd;
                if (t == 0) { pos = scv; sp_pos = hat_softplus(scv); }
                else {
                    sp_neg += hat_softplus(-scv);
                    cnt += (scv < pos) ? 1 : 0;
                }
            }
        }
        if (lane == 0) inv_rank = 1.0f / (float)(cnt + 1);
    }

    __shared__ float s_a[8], s_b[8], s_c[8];
    if (lane == 0) { s_a[wid] = sp_pos; s_b[wid] = sp_neg; s_c[wid] = inv_rank; }
    __syncthreads();
    if (wid == 0) {
        const int nw = blockDim.x >> 5;
        float a = (lane < nw) ? s_a[lane] : 0.0f;
        float b = (lane < nw) ? s_b[lane] : 0.0f;
        float c = (lane < nw) ? s_c[lane] : 0.0f;
        #pragma unroll
        for (int off = 4; off >= 1; off >>= 1) {
            a += __shfl_xor_sync(FULLMASK, a, off);
            b += __shfl_xor_sync(FULLMASK, b, off);
            c += __shfl_xor_sync(FULLMASK, c, off);
        }
        if (lane == 0) {
            atomicAdd(&g_acc[0], (double)a);
            atomicAdd(&g_acc[1], (double)b);
            atomicAdd(&g_acc[2], (double)c);
        }
    }
}

__global__ void hat_fin_kernel(float* out, int E_pos, int E_neg, int out_size) {
    double loss = g_acc[0] / (double)E_pos + g_acc[1] / (double)E_neg;
    out[0] = (float)loss;
    if (out_size > 1) out[1] = (float)(g_acc[2] / (double)E_pos);
}

extern "C" void kernel_launch(void* const* d_in, const int* in_sizes, int n_in,
                              void* d_out, int out_size) {
    const float* h  = (const float*)d_in[0];
    const int*   ps = (const int*)d_in[1];
    const int*   pd = (const int*)d_in[2];
    const int*   ns = (const int*)d_in[3];
    const int*   nd = (const int*)d_in[4];

    const int E_pos = in_sizes[1];
    const int E_neg = in_sizes[3];
    const int nn    = (E_pos > 0) ? (E_neg / E_pos) : 1;
    const int N     = in_sizes[0] / 64;   // D = 64 (fixed by dataset)

    if (nn == 5 && N <= ALPHA_CAP) {
        int a_threads = N * 16;
        hat_alpha_kernel<<<(a_threads + 255) / 256, 256>>>(h, N);
        const int gpb = 256 / 32;  // 8 groups (warps) per block
        const int blocks = (E_pos + gpb - 1) / gpb;
        hat_fused5_kernel<<<blocks, 256>>>(h, ps, pd, ns, nd,
                                           E_pos, E_neg, (float*)d_out, out_size);
    } else {
        hat_init_kernel<<<1, 1>>>();
        const int gpb = 256 / 32;
        hat_generic_kernel<<<(E_pos + gpb - 1) / gpb, 256>>>(h, ps, pd, ns, nd, E_pos, nn);
        hat_fin_kernel<<<1, 1>>>((float*)d_out, E_pos, E_neg, out_size);
    }
}

// round 6
// speedup vs baseline: 1.7382x; 1.7382x over previous
#include <cuda_runtime.h>
#include <cstdint>

#define HAT_EPS   1e-5f
#define ALPHA_CAP 2000000     // 8 MB static — proven safe in R1/R4
#define FULLMASK  0xffffffffu

// accumulators: [0]=sum softplus(pos), [1]=sum softplus(-neg), [2]=sum 1/(rank+1)
static __device__ double g_acc[3];          // zero-initialized at module load
static __device__ unsigned int g_done;      // ticket, reset by last block
static __device__ float g_ia[ALPHA_CAP];    // 1/max(1-||h_i||^2, eps)

__device__ __forceinline__ float hat_softplus(float x) {
    if (x > 30.0f) return x;
    return __logf(1.0f + __expf(x));
}

// ---------------------------------------------------------------------------
// Prepass: g_ia[i] = 1 / max(1 - ||h_i||^2, eps).  D=64, 16 lanes per node.
// ---------------------------------------------------------------------------
__global__ void __launch_bounds__(256) hat_alpha_kernel(const float* __restrict__ h, int N) {
    int tid  = blockIdx.x * blockDim.x + threadIdx.x;
    int node = tid >> 4;
    int sub  = tid & 15;
    if (node >= N) return;
    float4 a = __ldg((const float4*)(h + (size_t)node * 64) + sub);
    float s = fmaf(a.x, a.x, fmaf(a.y, a.y, fmaf(a.z, a.z, a.w * a.w)));
    s += __shfl_xor_sync(FULLMASK, s, 8);
    s += __shfl_xor_sync(FULLMASK, s, 4);
    s += __shfl_xor_sync(FULLMASK, s, 2);
    s += __shfl_xor_sync(FULLMASK, s, 1);
    if (sub == 0) g_ia[node] = 1.0f / fmaxf(1.0f - s, HAT_EPS);
}

// lanes 0-5 load src indices (pos, neg0..4), lanes 8-13 load dst indices
__device__ __forceinline__ int load_group_idx(
    int g, int lane,
    const int* __restrict__ ps, const int* __restrict__ pd,
    const int* __restrict__ ns, const int* __restrict__ nd)
{
    int idx = 0;
    if (lane == 0)                      idx = __ldg(&ps[g]);
    else if (lane <= 5)                 idx = __ldg(&ns[g * 5 + (lane - 1)]);
    else if (lane == 8)                 idx = __ldg(&pd[g]);
    else if (lane >= 9 && lane <= 13)   idx = __ldg(&nd[g * 5 + (lane - 9)]);
    return idx;
}

// ---------------------------------------------------------------------------
// Main kernel, NN=5: persistent grid-stride warps, one group per iteration.
// __launch_bounds__(256,4) -> 64-reg budget so ALL 12 row gathers stay in
// flight (the R4 build was silently serialized at 32 regs). Next group's
// indices are prefetched while current rows are in flight.
// ---------------------------------------------------------------------------
__global__ void __launch_bounds__(256, 4) hat_main5_kernel(
    const float* __restrict__ h,
    const int* __restrict__ ps, const int* __restrict__ pd,
    const int* __restrict__ ns, const int* __restrict__ nd,
    int E_pos, int E_neg, float* __restrict__ out, int out_size)
{
    const int lane = threadIdx.x & 31;
    const int wid  = threadIdx.x >> 5;
    const int half = lane >> 4;
    const int sub  = lane & 15;
    const int warp_global = blockIdx.x * (blockDim.x >> 5) + wid;
    const int total_warps = gridDim.x * (blockDim.x >> 5);

    const bool is_ia = (lane <= 5) || (lane >= 8 && lane <= 13);

    float acc_pos = 0.0f, acc_neg = 0.0f, acc_rr = 0.0f;   // lane 0 meaningful

    int g   = warp_global;
    int idx = (g < E_pos) ? load_group_idx(g, lane, ps, pd, ns, nd) : 0;

    while (g < E_pos) {
        // ia gather (2 MB array, L2-resident) — independent of row loads
        float ia = is_ia ? __ldg(&g_ia[idx]) : 0.0f;

        // ---- batch all 6 row-pair loads (256 B per row, fp32) ----
        float4 a[3], b[3];
        #pragma unroll
        for (int k = 0; k < 3; k++) {
            const int t = half + 2 * k;               // 0..5
            int src = __shfl_sync(FULLMASK, idx, t);
            int dst = __shfl_sync(FULLMASK, idx, 8 + t);
            a[k] = __ldg((const float4*)(h + (size_t)src * 64) + sub);
            b[k] = __ldg((const float4*)(h + (size_t)dst * 64) + sub);
        }

        // ---- prefetch next group's indices while rows are in flight ----
        const int gn = g + total_warps;
        int idx_next = (gn < E_pos) ? load_group_idx(gn, lane, ps, pd, ns, nd) : 0;

        // ---- per-half ||u-v||^2 reductions ----
        float sq[3];
        #pragma unroll
        for (int k = 0; k < 3; k++) {
            float dx = a[k].x - b[k].x, dy = a[k].y - b[k].y;
            float dz = a[k].z - b[k].z, dw = a[k].w - b[k].w;
            float s = fmaf(dx, dx, fmaf(dy, dy, fmaf(dz, dz, dw * dw)));
            s += __shfl_xor_sync(FULLMASK, s, 8);
            s += __shfl_xor_sync(FULLMASK, s, 4);
            s += __shfl_xor_sync(FULLMASK, s, 2);
            s += __shfl_xor_sync(FULLMASK, s, 1);
            sq[k] = s;   // uniform within each half
        }

        // ---- route distance t's sq to lane t (t = 0..5) ----
        float o0 = __shfl_xor_sync(FULLMASK, sq[0], 16);
        float o1 = __shfl_xor_sync(FULLMASK, sq[1], 16);
        float o2 = __shfl_xor_sync(FULLMASK, sq[2], 16);
        float ev = (lane >= 4) ? sq[2] : ((lane >= 2) ? sq[1] : sq[0]);
        float od = (lane >= 4) ? o2    : ((lane >= 2) ? o1    : o0);
        float sv = (lane & 1) ? od : ev;

        // inv_alpha product: lane t's src ia times dst ia (lane t+8)
        float ib = __shfl_sync(FULLMASK, ia, (lane & 7) + 8);
        float pr = ia * ib;

        // ---- ONE score + softplus pass covers all 6 distances ----
        float gam = fmaxf(fmaf(2.0f * sv, pr, 1.0f), 1.0f + HAT_EPS);
        float d   = __logf(gam + __fsqrt_rn(fmaf(gam, gam, -1.0f)));
        float scv = d * d;

        float pos = __shfl_sync(FULLMASK, scv, 0);
        unsigned ball = __ballot_sync(FULLMASK, scv < pos);  // -ns > -ps <=> ns < ps
        int cnt = __popc(ball & 0x3Eu);                      // lanes 1..5

        float arg = (lane == 0) ? scv : -scv;
        float sp  = hat_softplus(arg);
        float vneg = (lane >= 1 && lane <= 5) ? sp : 0.0f;
        vneg += __shfl_xor_sync(FULLMASK, vneg, 4);
        vneg += __shfl_xor_sync(FULLMASK, vneg, 2);
        vneg += __shfl_xor_sync(FULLMASK, vneg, 1);

        if (lane == 0) {
            acc_pos += sp;
            acc_neg += vneg;
            acc_rr  += 1.0f / (float)(cnt + 1);
        }

        g   = gn;
        idx = idx_next;
    }

    // ---- once per block: reduce -> global double atomics ----
    __shared__ float s_a[8], s_b[8], s_c[8];
    __shared__ bool  s_last;
    if (lane == 0) { s_a[wid] = acc_pos; s_b[wid] = acc_neg; s_c[wid] = acc_rr; }
    __syncthreads();
    if (wid == 0) {
        const int nw = blockDim.x >> 5;
        float va = (lane < nw) ? s_a[lane] : 0.0f;
        float vb = (lane < nw) ? s_b[lane] : 0.0f;
        float vc = (lane < nw) ? s_c[lane] : 0.0f;
        #pragma unroll
        for (int off = 4; off >= 1; off >>= 1) {
            va += __shfl_xor_sync(FULLMASK, va, off);
            vb += __shfl_xor_sync(FULLMASK, vb, off);
            vc += __shfl_xor_sync(FULLMASK, vc, off);
        }
        if (lane == 0) {
            atomicAdd(&g_acc[0], (double)va);
            atomicAdd(&g_acc[1], (double)vb);
            atomicAdd(&g_acc[2], (double)vc);
            __threadfence();
            unsigned ticket = atomicAdd(&g_done, 1u);
            s_last = (ticket == gridDim.x - 1);
        }
    }
    __syncthreads();

    // ---- last block finalizes and resets state for the next graph replay ----
    if (s_last && threadIdx.x == 0) {
        volatile double* acc = (volatile double*)g_acc;
        double a = acc[0], b = acc[1], c = acc[2];
        out[0] = (float)(a / (double)E_pos + b / (double)E_neg);
        if (out_size > 1) out[1] = (float)(c / (double)E_pos);
        g_acc[0] = 0.0; g_acc[1] = 0.0; g_acc[2] = 0.0;
        g_done = 0u;
        __threadfence();
    }
}

// ---------------------------------------------------------------------------
// Generic fallback (any nn or N > ALPHA_CAP), self-contained.
// ---------------------------------------------------------------------------
__global__ void hat_init_kernel() {
    g_acc[0] = 0.0; g_acc[1] = 0.0; g_acc[2] = 0.0;
}

__global__ void __launch_bounds__(256) hat_generic_kernel(
    const float* __restrict__ h,
    const int* __restrict__ ps, const int* __restrict__ pd,
    const int* __restrict__ ns, const int* __restrict__ nd,
    int E_pos, int nn)
{
    const int lane = threadIdx.x & 31;
    const int wid  = threadIdx.x >> 5;
    const int g    = blockIdx.x * (blockDim.x >> 5) + wid;

    float sp_pos = 0.0f, sp_neg = 0.0f, inv_rank = 0.0f;

    if (g < E_pos) {
        float pos = 0.0f;
        int   cnt = 0;
        for (int t = 0; t <= nn; t++) {
            int src, dst;
            if (t == 0) { src = ps[g]; dst = pd[g]; }
            else {
                size_t e = (size_t)g * nn + (t - 1);
                src = ns[e]; dst = nd[e];
            }
            const float2* up = (const float2*)(h + (size_t)src * 64);
            const float2* vp = (const float2*)(h + (size_t)dst * 64);
            float2 a = up[lane], b = vp[lane];
            float dx = a.x - b.x, dy = a.y - b.y;
            float sq = dx * dx + dy * dy;
            float uu = a.x * a.x + a.y * a.y;
            float vv = b.x * b.x + b.y * b.y;
            #pragma unroll
            for (int off = 16; off >= 1; off >>= 1) {
                sq += __shfl_xor_sync(FULLMASK, sq, off);
                uu += __shfl_xor_sync(FULLMASK, uu, off);
                vv += __shfl_xor_sync(FULLMASK, vv, off);
            }
            if (lane == 0) {
                float alpha = fmaxf(1.0f - uu, HAT_EPS);
                float beta  = fmaxf(1.0f - vv, HAT_EPS);
                float gam   = fmaxf(1.0f + 2.0f * sq / (alpha * beta), 1.0f + HAT_EPS);
                float dd    = __logf(gam + __fsqrt_rn(fmaf(gam, gam, -1.0f)));
                float scv   = dd * dd;
                if (t == 0) { pos = scv; sp_pos = hat_softplus(scv); }
                else {
                    sp_neg += hat_softplus(-scv);
                    cnt += (scv < pos) ? 1 : 0;
                }
            }
        }
        if (lane == 0) inv_rank = 1.0f / (float)(cnt + 1);
    }

    __shared__ float s_a[8], s_b[8], s_c[8];
    if (lane == 0) { s_a[wid] = sp_pos; s_b[wid] = sp_neg; s_c[wid] = inv_rank; }
    __syncthreads();
    if (wid == 0) {
        const int nw = blockDim.x >> 5;
        float a = (lane < nw) ? s_a[lane] : 0.0f;
        float b = (lane < nw) ? s_b[lane] : 0.0f;
        float c = (lane < nw) ? s_c[lane] : 0.0f;
        #pragma unroll
        for (int off = 4; off >= 1; off >>= 1) {
            a += __shfl_xor_sync(FULLMASK, a, off);
            b += __shfl_xor_sync(FULLMASK, b, off);
            c += __shfl_xor_sync(FULLMASK, c, off);
        }
        if (lane == 0) {
            atomicAdd(&g_acc[0], (double)a);
            atomicAdd(&g_acc[1], (double)b);
            atomicAdd(&g_acc[2], (double)c);
        }
    }
}

__global__ void hat_fin_kernel(float* out, int E_pos, int E_neg, int out_size) {
    double loss = g_acc[0] / (double)E_pos + g_acc[1] / (double)E_neg;
    out[0] = (float)loss;
    if (out_size > 1) out[1] = (float)(g_acc[2] / (double)E_pos);
}

extern "C" void kernel_launch(void* const* d_in, const int* in_sizes, int n_in,
                              void* d_out, int out_size) {
    const float* h  = (const float*)d_in[0];
    const int*   ps = (const int*)d_in[1];
    const int*   pd = (const int*)d_in[2];
    const int*   ns = (const int*)d_in[3];
    const int*   nd = (const int*)d_in[4];

    const int E_pos = in_sizes[1];
    const int E_neg = in_sizes[3];
    const int nn    = (E_pos > 0) ? (E_neg / E_pos) : 1;
    const int N     = in_sizes[0] / 64;   // D = 64 (fixed by dataset)

    if (nn == 5 && N <= ALPHA_CAP) {
        int p_threads = N * 16;
        hat_alpha_kernel<<<(p_threads + 255) / 256, 256>>>(h, N);
        // ~4 blocks/SM resident (launch_bounds pairs with this); extra blocks
        // just wave-schedule; grid-stride keeps correctness for any grid.
        int blocks = 1184;
        int max_blocks = (E_pos + 7) / 8;           // >= 1 group per warp
        if (blocks > max_blocks) blocks = max_blocks;
        hat_main5_kernel<<<blocks, 256>>>(h, ps, pd, ns, nd,
                                          E_pos, E_neg, (float*)d_out, out_size);
    } else {
        hat_init_kernel<<<1, 1>>>();
        const int gpb = 256 / 32;
        hat_generic_kernel<<<(E_pos + gpb - 1) / gpb, 256>>>(h, ps, pd, ns, nd, E_pos, nn);
        hat_fin_kernel<<<1, 1>>>((float*)d_out, E_pos, E_neg, out_size);
    }
}

// round 7
// speedup vs baseline: 1.7478x; 1.0055x over previous
#include <cuda_runtime.h>
#include <cuda_fp16.h>
#include <cstdint>

#define HAT_EPS   1e-5f
#define H16_CAP   524288      // fp16 fast-path node cap (64 MB static, L2-resident)
#define FULLMASK  0xffffffffu

// accumulators: [0]=sum softplus(pos), [1]=sum softplus(-neg), [2]=sum 1/(rank+1)
static __device__ double g_acc[3];            // zero-initialized at module load
static __device__ unsigned int g_done;        // ticket, reset by last block
static __device__ float  g_ia[H16_CAP];       // 1/max(1-||h_i||^2, eps) (fp32, exact)
static __device__ __half g_h16[(size_t)H16_CAP * 64];  // fp16 copy of h

__device__ __forceinline__ float hat_softplus(float x) {
    if (x > 30.0f) return x;
    return __logf(1.0f + __expf(x));
}

// ---------------------------------------------------------------------------
// Prepass: per node, ia = 1/max(1-||h||^2, eps) computed from fp32, and the
// fp16 row copy written. 16 lanes per node, float4 in / uint2 (4 halves) out.
// ---------------------------------------------------------------------------
__global__ void __launch_bounds__(256) hat_prep_kernel(const float* __restrict__ h, int N) {
    int tid  = blockIdx.x * blockDim.x + threadIdx.x;
    int node = tid >> 4;
    int sub  = tid & 15;
    if (node >= N) return;
    float4 a = __ldg((const float4*)(h + (size_t)node * 64) + sub);

    half2 lo = __float22half2_rn(make_float2(a.x, a.y));
    half2 hi = __float22half2_rn(make_float2(a.z, a.w));
    uint2 pack;
    pack.x = *(unsigned*)&lo;
    pack.y = *(unsigned*)&hi;
    *((uint2*)(g_h16 + (size_t)node * 64) + sub) = pack;

    float s = fmaf(a.x, a.x, fmaf(a.y, a.y, fmaf(a.z, a.z, a.w * a.w)));
    s += __shfl_xor_sync(FULLMASK, s, 8);
    s += __shfl_xor_sync(FULLMASK, s, 4);
    s += __shfl_xor_sync(FULLMASK, s, 2);
    s += __shfl_xor_sync(FULLMASK, s, 1);
    if (sub == 0) g_ia[node] = 1.0f / fmaxf(1.0f - s, HAT_EPS);
}

// lanes 0-5 load src indices (pos, neg0..4), lanes 8-13 load dst indices
__device__ __forceinline__ int load_group_idx(
    int g, int lane,
    const int* __restrict__ ps, const int* __restrict__ pd,
    const int* __restrict__ ns, const int* __restrict__ nd)
{
    int idx = 0;
    if (lane == 0)                      idx = __ldg(&ps[g]);
    else if (lane <= 5)                 idx = __ldg(&ns[g * 5 + (lane - 1)]);
    else if (lane == 8)                 idx = __ldg(&pd[g]);
    else if (lane >= 9 && lane <= 13)   idx = __ldg(&nd[g * 5 + (lane - 9)]);
    return idx;
}

// ---------------------------------------------------------------------------
// Main kernel, NN=5: persistent grid-stride warps (R6 structure verbatim),
// but gathering 128-B fp16 rows from the L2-resident compacted copy.
// ---------------------------------------------------------------------------
__global__ void __launch_bounds__(256, 4) hat_main5_kernel(
    const int* __restrict__ ps, const int* __restrict__ pd,
    const int* __restrict__ ns, const int* __restrict__ nd,
    int E_pos, int E_neg, float* __restrict__ out, int out_size)
{
    const int lane = threadIdx.x & 31;
    const int wid  = threadIdx.x >> 5;
    const int half = lane >> 4;
    const int sub  = lane & 15;
    const int warp_global = blockIdx.x * (blockDim.x >> 5) + wid;
    const int total_warps = gridDim.x * (blockDim.x >> 5);

    const bool is_ia = (lane <= 5) || (lane >= 8 && lane <= 13);

    float acc_pos = 0.0f, acc_neg = 0.0f, acc_rr = 0.0f;   // lane 0 meaningful

    int g   = warp_global;
    int idx = (g < E_pos) ? load_group_idx(g, lane, ps, pd, ns, nd) : 0;

    while (g < E_pos) {
        float ia = is_ia ? __ldg(&g_ia[idx]) : 0.0f;

        // ---- batch all 6 row-pair loads (fp16 rows: 8 B per lane) ----
        uint2 ra[3], rb[3];
        #pragma unroll
        for (int k = 0; k < 3; k++) {
            const int t = half + 2 * k;               // 0..5
            int src = __shfl_sync(FULLMASK, idx, t);
            int dst = __shfl_sync(FULLMASK, idx, 8 + t);
            ra[k] = __ldg((const uint2*)(g_h16 + (size_t)src * 64) + sub);
            rb[k] = __ldg((const uint2*)(g_h16 + (size_t)dst * 64) + sub);
        }

        // ---- prefetch next group's indices while rows are in flight ----
        const int gn = g + total_warps;
        int idx_next = (gn < E_pos) ? load_group_idx(gn, lane, ps, pd, ns, nd) : 0;

        // ---- per-half ||u-v||^2 reductions ----
        float sq[3];
        #pragma unroll
        for (int k = 0; k < 3; k++) {
            float2 ax = __half22float2(*(half2*)&ra[k].x);
            float2 ay = __half22float2(*(half2*)&ra[k].y);
            float2 bx = __half22float2(*(half2*)&rb[k].x);
            float2 by = __half22float2(*(half2*)&rb[k].y);
            float d0 = ax.x - bx.x, d1 = ax.y - bx.y;
            float d2 = ay.x - by.x, d3 = ay.y - by.y;
            float s = fmaf(d0, d0, fmaf(d1, d1, fmaf(d2, d2, d3 * d3)));
            s += __shfl_xor_sync(FULLMASK, s, 8);
            s += __shfl_xor_sync(FULLMASK, s, 4);
            s += __shfl_xor_sync(FULLMASK, s, 2);
            s += __shfl_xor_sync(FULLMASK, s, 1);
            sq[k] = s;   // uniform within each half
        }

        // ---- route distance t's sq to lane t (t = 0..5) ----
        float o0 = __shfl_xor_sync(FULLMASK, sq[0], 16);
        float o1 = __shfl_xor_sync(FULLMASK, sq[1], 16);
        float o2 = __shfl_xor_sync(FULLMASK, sq[2], 16);
        float ev = (lane >= 4) ? sq[2] : ((lane >= 2) ? sq[1] : sq[0]);
        float od = (lane >= 4) ? o2    : ((lane >= 2) ? o1    : o0);
        float sv = (lane & 1) ? od : ev;

        // inv_alpha product: lane t's src ia times dst ia (lane t+8)
        float ib = __shfl_sync(FULLMASK, ia, (lane & 7) + 8);
        float pr = ia * ib;

        // ---- ONE score + softplus pass covers all 6 distances ----
        float gam = fmaxf(fmaf(2.0f * sv, pr, 1.0f), 1.0f + HAT_EPS);
        float d   = __logf(gam + __fsqrt_rn(fmaf(gam, gam, -1.0f)));
        float scv = d * d;

        float pos = __shfl_sync(FULLMASK, scv, 0);
        unsigned ball = __ballot_sync(FULLMASK, scv < pos);  // -ns > -ps <=> ns < ps
        int cnt = __popc(ball & 0x3Eu);                      // lanes 1..5

        float arg = (lane == 0) ? scv : -scv;
        float sp  = hat_softplus(arg);
        float vneg = (lane >= 1 && lane <= 5) ? sp : 0.0f;
        vneg += __shfl_xor_sync(FULLMASK, vneg, 4);
        vneg += __shfl_xor_sync(FULLMASK, vneg, 2);
        vneg += __shfl_xor_sync(FULLMASK, vneg, 1);

        if (lane == 0) {
            acc_pos += sp;
            acc_neg += vneg;
            acc_rr  += 1.0f / (float)(cnt + 1);
        }

        g   = gn;
        idx = idx_next;
    }

    // ---- once per block: reduce -> global double atomics ----
    __shared__ float s_a[8], s_b[8], s_c[8];
    __shared__ bool  s_last;
    if (lane == 0) { s_a[wid] = acc_pos; s_b[wid] = acc_neg; s_c[wid] = acc_rr; }
    __syncthreads();
    if (wid == 0) {
        const int nw = blockDim.x >> 5;
        float va = (lane < nw) ? s_a[lane] : 0.0f;
        float vb = (lane < nw) ? s_b[lane] : 0.0f;
        float vc = (lane < nw) ? s_c[lane] : 0.0f;
        #pragma unroll
        for (int off = 4; off >= 1; off >>= 1) {
            va += __shfl_xor_sync(FULLMASK, va, off);
            vb += __shfl_xor_sync(FULLMASK, vb, off);
            vc += __shfl_xor_sync(FULLMASK, vc, off);
        }
        if (lane == 0) {
            atomicAdd(&g_acc[0], (double)va);
            atomicAdd(&g_acc[1], (double)vb);
            atomicAdd(&g_acc[2], (double)vc);
            __threadfence();
            unsigned ticket = atomicAdd(&g_done, 1u);
            s_last = (ticket == gridDim.x - 1);
        }
    }
    __syncthreads();

    // ---- last block finalizes and resets state for the next graph replay ----
    if (s_last && threadIdx.x == 0) {
        volatile double* acc = (volatile double*)g_acc;
        double a = acc[0], b = acc[1], c = acc[2];
        out[0] = (float)(a / (double)E_pos + b / (double)E_neg);
        if (out_size > 1) out[1] = (float)(c / (double)E_pos);
        g_acc[0] = 0.0; g_acc[1] = 0.0; g_acc[2] = 0.0;
        g_done = 0u;
        __threadfence();
    }
}

// ---------------------------------------------------------------------------
// Generic fallback (any nn or N > H16_CAP), fp32, self-contained.
// ---------------------------------------------------------------------------
__global__ void hat_init_kernel() {
    g_acc[0] = 0.0; g_acc[1] = 0.0; g_acc[2] = 0.0;
}

__global__ void __launch_bounds__(256) hat_generic_kernel(
    const float* __restrict__ h,
    const int* __restrict__ ps, const int* __restrict__ pd,
    const int* __restrict__ ns, const int* __restrict__ nd,
    int E_pos, int nn)
{
    const int lane = threadIdx.x & 31;
    const int wid  = threadIdx.x >> 5;
    const int g    = blockIdx.x * (blockDim.x >> 5) + wid;

    float sp_pos = 0.0f, sp_neg = 0.0f, inv_rank = 0.0f;

    if (g < E_pos) {
        float pos = 0.0f;
        int   cnt = 0;
        for (int t = 0; t <= nn; t++) {
            int src, dst;
            if (t == 0) { src = ps[g]; dst = pd[g]; }
            else {
                size_t e = (size_t)g * nn + (t - 1);
                src = ns[e]; dst = nd[e];
            }
            const float2* up = (const float2*)(h + (size_t)src * 64);
            const float2* vp = (const float2*)(h + (size_t)dst * 64);
            float2 a = up[lane], b = vp[lane];
            float dx = a.x - b.x, dy = a.y - b.y;
            float sq = dx * dx + dy * dy;
            float uu = a.x * a.x + a.y * a.y;
            float vv = b.x * b.x + b.y * b.y;
            #pragma unroll
            for (int off = 16; off >= 1; off >>= 1) {
                sq += __shfl_xor_sync(FULLMASK, sq, off);
                uu += __shfl_xor_sync(FULLMASK, uu, off);
                vv += __shfl_xor_sync(FULLMASK, vv, off);
            }
            if (lane == 0) {
                float alpha = fmaxf(1.0f - uu, HAT_EPS);
                float beta  = fmaxf(1.0f - vv, HAT_EPS);
                float gam   = fmaxf(1.0f + 2.0f * sq / (alpha * beta), 1.0f + HAT_EPS);
                float dd    = __logf(gam + __fsqrt_rn(fmaf(gam, gam, -1.0f)));
                float scv   = dd * dd;
                if (t == 0) { pos = scv; sp_pos = hat_softplus(scv); }
                else {
                    sp_neg += hat_softplus(-scv);
                    cnt += (scv < pos) ? 1 : 0;
                }
            }
        }
        if (lane == 0) inv_rank = 1.0f / (float)(cnt + 1);
    }

    __shared__ float s_a[8], s_b[8], s_c[8];
    if (lane == 0) { s_a[wid] = sp_pos; s_b[wid] = sp_neg; s_c[wid] = inv_rank; }
    __syncthreads();
    if (wid == 0) {
        const int nw = blockDim.x >> 5;
        float a = (lane < nw) ? s_a[lane] : 0.0f;
        float b = (lane < nw) ? s_b[lane] : 0.0f;
        float c = (lane < nw) ? s_c[lane] : 0.0f;
        #pragma unroll
        for (int off = 4; off >= 1; off >>= 1) {
            a += __shfl_xor_sync(FULLMASK, a, off);
            b += __shfl_xor_sync(FULLMASK, b, off);
            c += __shfl_xor_sync(FULLMASK, c, off);
        }
        if (lane == 0) {
            atomicAdd(&g_acc[0], (double)a);
            atomicAdd(&g_acc[1], (double)b);
            atomicAdd(&g_acc[2], (double)c);
        }
    }
}

__global__ void hat_fin_kernel(float* out, int E_pos, int E_neg, int out_size) {
    double loss = g_acc[0] / (double)E_pos + g_acc[1] / (double)E_neg;
    out[0] = (float)loss;
    if (out_size > 1) out[1] = (float)(g_acc[2] / (double)E_pos);
}

extern "C" void kernel_launch(void* const* d_in, const int* in_sizes, int n_in,
                              void* d_out, int out_size) {
    const float* h  = (const float*)d_in[0];
    const int*   ps = (const int*)d_in[1];
    const int*   pd = (const int*)d_in[2];
    const int*   ns = (const int*)d_in[3];
    const int*   nd = (const int*)d_in[4];

    const int E_pos = in_sizes[1];
    const int E_neg = in_sizes[3];
    const int nn    = (E_pos > 0) ? (E_neg / E_pos) : 1;
    const int N     = in_sizes[0] / 64;   // D = 64 (fixed by dataset)

    if (nn == 5 && N <= H16_CAP) {
        int p_threads = N * 16;
        hat_prep_kernel<<<(p_threads + 255) / 256, 256>>>(h, N);
        int blocks = 1184;
        int max_blocks = (E_pos + 7) / 8;           // >= 1 group per warp
        if (blocks > max_blocks) blocks = max_blocks;
        hat_main5_kernel<<<blocks, 256>>>(ps, pd, ns, nd,
                                          E_pos, E_neg, (float*)d_out, out_size);
    } else {
        hat_init_kernel<<<1, 1>>>();
        const int gpb = 256 / 32;
        hat_generic_kernel<<<(E_pos + gpb - 1) / gpb, 256>>>(h, ps, pd, ns, nd, E_pos, nn);
        hat_fin_kernel<<<1, 1>>>((float*)d_out, E_pos, E_neg, out_size);
    }
}

// round 8
// speedup vs baseline: 2.5601x; 1.4648x over previous
#include <cuda_runtime.h>
#include <cuda_fp16.h>
#include <cstdint>

#define HAT_EPS   1e-5f
#define H16_CAP   524288      // fp16 fast-path node cap (64 MB static, L2-resident)
#define FULLMASK  0xffffffffu

// accumulators: [0]=sum softplus(pos), [1]=sum softplus(-neg), [2]=sum 1/(rank+1)
static __device__ double g_acc[3];            // zero-initialized at module load
static __device__ unsigned int g_done;        // ticket, reset by last block
static __device__ float  g_ia[H16_CAP];       // 1/max(1-||h_i||^2, eps) (fp32, exact)
static __device__ __half g_h16[(size_t)H16_CAP * 64];  // fp16 copy of h

__device__ __forceinline__ float hat_softplus(float x) {
    if (x > 30.0f) return x;
    return __logf(1.0f + __expf(x));
}

// ---------------------------------------------------------------------------
// Prepass: per node, ia = 1/max(1-||h||^2, eps) from fp32, fp16 row copy out.
// ---------------------------------------------------------------------------
__global__ void __launch_bounds__(256) hat_prep_kernel(const float* __restrict__ h, int N) {
    int tid  = blockIdx.x * blockDim.x + threadIdx.x;
    int node = tid >> 4;
    int sub  = tid & 15;
    if (node >= N) return;
    float4 a = __ldg((const float4*)(h + (size_t)node * 64) + sub);

    half2 lo = __float22half2_rn(make_float2(a.x, a.y));
    half2 hi = __float22half2_rn(make_float2(a.z, a.w));
    uint2 pack;
    pack.x = *(unsigned*)&lo;
    pack.y = *(unsigned*)&hi;
    *((uint2*)(g_h16 + (size_t)node * 64) + sub) = pack;

    float s = fmaf(a.x, a.x, fmaf(a.y, a.y, fmaf(a.z, a.z, a.w * a.w)));
    s += __shfl_xor_sync(FULLMASK, s, 8);
    s += __shfl_xor_sync(FULLMASK, s, 4);
    s += __shfl_xor_sync(FULLMASK, s, 2);
    s += __shfl_xor_sync(FULLMASK, s, 1);
    if (sub == 0) g_ia[node] = 1.0f / fmaxf(1.0f - s, HAT_EPS);
}

// ---------------------------------------------------------------------------
// Pair index loader. Distance d (0..11; 0..5 = group A, 6..11 = group B):
//   src idx lives on lane(d) = 2*(d%6) + (d/6)  (lanes 0..11)
//   dst idx lives on lane(d) + 16               (lanes 16..27)
// Pair m -> groups g0 = 2m (A) and g0+1 (B).
// ---------------------------------------------------------------------------
__device__ __forceinline__ int load_pair_idx(
    int m, int P, int E_pos, bool is_src, bool is_dst, int dGrp, int dOff,
    const int* __restrict__ ps, const int* __restrict__ pd,
    const int* __restrict__ ns, const int* __restrict__ nd)
{
    if (m >= P || !(is_src || is_dst)) return 0;
    int g = 2 * m + dGrp;
    if (g >= E_pos) return 0;
    const int* b0 = is_src ? ps : pd;
    const int* b5 = is_src ? ns : nd;
    return (dOff == 0) ? __ldg(&b0[g]) : __ldg(&b5[g * 5 + dOff - 1]);
}

// ---------------------------------------------------------------------------
// Main kernel, NN=5: persistent warps, TWO groups (one pair) per iteration.
// 8-lane teams (uint4 = 16 B fp16 per lane -> 128 B row); team q handles
// distances 3q+r over rounds r=0..2. Scores for all 12 distances computed in
// one pass on lanes 0..11 (even = group A, odd = group B).
// ---------------------------------------------------------------------------
__global__ void __launch_bounds__(256, 4) hat_main5_kernel(
    const int* __restrict__ ps, const int* __restrict__ pd,
    const int* __restrict__ ns, const int* __restrict__ nd,
    int E_pos, int E_neg, float* __restrict__ out, int out_size)
{
    const int lane  = threadIdx.x & 31;
    const int wid   = threadIdx.x >> 5;
    const int tlane = lane & 7;           // lane within 8-lane team
    const int q     = lane >> 3;          // team id 0..3
    const int warp_global = blockIdx.x * (blockDim.x >> 5) + wid;
    const int total_warps = gridDim.x * (blockDim.x >> 5);
    const int P = (E_pos + 1) >> 1;       // number of pairs

    // ---- hoisted lane-role constants ----
    const bool is_src = (lane < 12);
    const bool is_dst = (lane >= 16 && lane < 28);
    const int  dBase  = is_src ? lane : (is_dst ? (lane - 16) : 0);
    const int  dIdx   = (dBase & 1) * 6 + (dBase >> 1);   // distance owned (idx lanes)
    const int  dGrp   = dIdx / 6;                          // 0 -> g0, 1 -> g1
    const int  dOff   = dIdx % 6;                          // 0 = pos, 1..5 = neg slot
    // row-load source lanes per round (loop-invariant per lane)
    int slr[3];
    #pragma unroll
    for (int r = 0; r < 3; r++) {
        int dd = 3 * q + r;
        slr[r] = 2 * (dd % 6) + (dd / 6);
    }
    // score routing (lanes 0..11): this lane scores distance dS
    const int dS        = (lane & 1) * 6 + (lane >> 1);
    const int sTeamLane = (dS / 3) * 8;
    const int sR        = dS % 3;
    const unsigned cntMask = (lane & 1) ? 0xAA8u : 0x554u;  // neg lanes of own group

    float acc_pos = 0.0f, acc_neg = 0.0f, acc_rr = 0.0f;   // lanes 0 (A) and 1 (B)

    int m   = warp_global;
    int idx = load_pair_idx(m, P, E_pos, is_src, is_dst, dGrp, dOff, ps, pd, ns, nd);

    while (m < P) {
        const bool hasB = (2 * m + 1) < E_pos;
        float ia = (is_src || is_dst) ? __ldg(&g_ia[idx]) : 0.0f;

        // ---- 3 rounds x 4 teams: all 12 row pairs in flight ----
        uint4 ra[3], rb[3];
        #pragma unroll
        for (int r = 0; r < 3; r++) {
            int src = __shfl_sync(FULLMASK, idx, slr[r]);
            int dst = __shfl_sync(FULLMASK, idx, slr[r] + 16);
            ra[r] = __ldg((const uint4*)(g_h16 + (size_t)src * 64) + tlane);
            rb[r] = __ldg((const uint4*)(g_h16 + (size_t)dst * 64) + tlane);
        }

        // ---- prefetch next pair's indices while rows are in flight ----
        const int mn = m + total_warps;
        int idx_next = load_pair_idx(mn, P, E_pos, is_src, is_dst, dGrp, dOff,
                                     ps, pd, ns, nd);

        // ---- per-team ||u-v||^2: hsub2 diffs, fp32 square-accumulate ----
        float sq3[3];
        #pragma unroll
        for (int r = 0; r < 3; r++) {
            half2 d0 = __hsub2(*(half2*)&ra[r].x, *(half2*)&rb[r].x);
            half2 d1 = __hsub2(*(half2*)&ra[r].y, *(half2*)&rb[r].y);
            half2 d2 = __hsub2(*(half2*)&ra[r].z, *(half2*)&rb[r].z);
            half2 d3 = __hsub2(*(half2*)&ra[r].w, *(half2*)&rb[r].w);
            float2 f0 = __half22float2(d0);
            float2 f1 = __half22float2(d1);
            float2 f2 = __half22float2(d2);
            float2 f3 = __half22float2(d3);
            float s = f0.x * f0.x;
            s = fmaf(f0.y, f0.y, s);
            s = fmaf(f1.x, f1.x, s);
            s = fmaf(f1.y, f1.y, s);
            s = fmaf(f2.x, f2.x, s);
            s = fmaf(f2.y, f2.y, s);
            s = fmaf(f3.x, f3.x, s);
            s = fmaf(f3.y, f3.y, s);
            s += __shfl_xor_sync(FULLMASK, s, 1);
            s += __shfl_xor_sync(FULLMASK, s, 2);
            s += __shfl_xor_sync(FULLMASK, s, 4);
            sq3[r] = s;   // uniform within team
        }

        // ---- route: score lane (0..11) pulls its distance's sq ----
        float x0 = __shfl_sync(FULLMASK, sq3[0], sTeamLane);
        float x1 = __shfl_sync(FULLMASK, sq3[1], sTeamLane);
        float x2 = __shfl_sync(FULLMASK, sq3[2], sTeamLane);
        float sv = (sR == 0) ? x0 : ((sR == 1) ? x1 : x2);

        // ia product (src on own lane, dst at lane+16)
        float ib = __shfl_sync(FULLMASK, ia, (lane & 15) + 16);
        float pr = ia * ib;

        // ---- one score pass for all 12 distances ----
        float gam = fmaxf(fmaf(2.0f * sv, pr, 1.0f), 1.0f + HAT_EPS);
        float d   = __logf(gam + __fsqrt_rn(fmaf(gam, gam, -1.0f)));
        float scv = d * d;

        float pos = __shfl_sync(FULLMASK, scv, lane & 1);   // lane0=posA, lane1=posB
        unsigned ball = __ballot_sync(FULLMASK, scv < pos);

        float arg = (lane < 2) ? scv : -scv;
        float sp  = hat_softplus(arg);
        float vneg = (lane >= 2 && lane < 12) ? sp : 0.0f;
        // parity-preserving butterfly: evens sum group A, odds sum group B
        vneg += __shfl_xor_sync(FULLMASK, vneg, 2);
        vneg += __shfl_xor_sync(FULLMASK, vneg, 4);
        vneg += __shfl_xor_sync(FULLMASK, vneg, 8);
        vneg += __shfl_xor_sync(FULLMASK, vneg, 16);

        if (lane == 0) {
            acc_pos += sp;
            acc_neg += vneg;
            acc_rr  += 1.0f / (float)(__popc(ball & cntMask) + 1);
        } else if (lane == 1 && hasB) {
            acc_pos += sp;
            acc_neg += vneg;
            acc_rr  += 1.0f / (float)(__popc(ball & cntMask) + 1);
        }

        m   = mn;
        idx = idx_next;
    }

    // fold lane 1 (group B accumulator) into lane 0
    acc_pos += __shfl_down_sync(FULLMASK, acc_pos, 1);
    acc_neg += __shfl_down_sync(FULLMASK, acc_neg, 1);
    acc_rr  += __shfl_down_sync(FULLMASK, acc_rr, 1);

    // ---- once per block: reduce -> global double atomics ----
    __shared__ float s_a[8], s_b[8], s_c[8];
    __shared__ bool  s_last;
    if (lane == 0) { s_a[wid] = acc_pos; s_b[wid] = acc_neg; s_c[wid] = acc_rr; }
    __syncthreads();
    if (wid == 0) {
        const int nw = blockDim.x >> 5;
        float va = (lane < nw) ? s_a[lane] : 0.0f;
        float vb = (lane < nw) ? s_b[lane] : 0.0f;
        float vc = (lane < nw) ? s_c[lane] : 0.0f;
        #pragma unroll
        for (int off = 4; off >= 1; off >>= 1) {
            va += __shfl_xor_sync(FULLMASK, va, off);
            vb += __shfl_xor_sync(FULLMASK, vb, off);
            vc += __shfl_xor_sync(FULLMASK, vc, off);
        }
        if (lane == 0) {
            atomicAdd(&g_acc[0], (double)va);
            atomicAdd(&g_acc[1], (double)vb);
            atomicAdd(&g_acc[2], (double)vc);
            __threadfence();
            unsigned ticket = atomicAdd(&g_done, 1u);
            s_last = (ticket == gridDim.x - 1);
        }
    }
    __syncthreads();

    // ---- last block finalizes and resets state for the next graph replay ----
    if (s_last && threadIdx.x == 0) {
        volatile double* acc = (volatile double*)g_acc;
        double a = acc[0], b = acc[1], c = acc[2];
        out[0] = (float)(a / (double)E_pos + b / (double)E_neg);
        if (out_size > 1) out[1] = (float)(c / (double)E_pos);
        g_acc[0] = 0.0; g_acc[1] = 0.0; g_acc[2] = 0.0;
        g_done = 0u;
        __threadfence();
    }
}

// ---------------------------------------------------------------------------
// Generic fallback (any nn or N > H16_CAP), fp32, self-contained.
// ---------------------------------------------------------------------------
__global__ void hat_init_kernel() {
    g_acc[0] = 0.0; g_acc[1] = 0.0; g_acc[2] = 0.0;
}

__global__ void __launch_bounds__(256) hat_generic_kernel(
    const float* __restrict__ h,
    const int* __restrict__ ps, const int* __restrict__ pd,
    const int* __restrict__ ns, const int* __restrict__ nd,
    int E_pos, int nn)
{
    const int lane = threadIdx.x & 31;
    const int wid  = threadIdx.x >> 5;
    const int g    = blockIdx.x * (blockDim.x >> 5) + wid;

    float sp_pos = 0.0f, sp_neg = 0.0f, inv_rank = 0.0f;

    if (g < E_pos) {
        float pos = 0.0f;
        int   cnt = 0;
        for (int t = 0; t <= nn; t++) {
            int src, dst;
            if (t == 0) { src = ps[g]; dst = pd[g]; }
            else {
                size_t e = (size_t)g * nn + (t - 1);
                src = ns[e]; dst = nd[e];
            }
            const float2* up = (const float2*)(h + (size_t)src * 64);
            const float2* vp = (const float2*)(h + (size_t)dst * 64);
            float2 a = up[lane], b = vp[lane];
            float dx = a.x - b.x, dy = a.y - b.y;
            float sq = dx * dx + dy * dy;
            float uu = a.x * a.x + a.y * a.y;
            float vv = b.x * b.x + b.y * b.y;
            #pragma unroll
            for (int off = 16; off >= 1; off >>= 1) {
                sq += __shfl_xor_sync(FULLMASK, sq, off);
                uu += __shfl_xor_sync(FULLMASK, uu, off);
                vv += __shfl_xor_sync(FULLMASK, vv, off);
            }
            if (lane == 0) {
                float alpha = fmaxf(1.0f - uu, HAT_EPS);
                float beta  = fmaxf(1.0f - vv, HAT_EPS);
                float gam   = fmaxf(1.0f + 2.0f * sq / (alpha * beta), 1.0f + HAT_EPS);
                float dd    = __logf(gam + __fsqrt_rn(fmaf(gam, gam, -1.0f)));
                float scv   = dd * dd;
                if (t == 0) { pos = scv; sp_pos = hat_softplus(scv); }
                else {
                    sp_neg += hat_softplus(-scv);
                    cnt += (scv < pos) ? 1 : 0;
                }
            }
        }
        if (lane == 0) inv_rank = 1.0f / (float)(cnt + 1);
    }

    __shared__ float s_a[8], s_b[8], s_c[8];
    if (lane == 0) { s_a[wid] = sp_pos; s_b[wid] = sp_neg; s_c[wid] = inv_rank; }
    __syncthreads();
    if (wid == 0) {
        const int nw = blockDim.x >> 5;
        float a = (lane < nw) ? s_a[lane] : 0.0f;
        float b = (lane < nw) ? s_b[lane] : 0.0f;
        float c = (lane < nw) ? s_c[lane] : 0.0f;
        #pragma unroll
        for (int off = 4; off >= 1; off >>= 1) {
            a += __shfl_xor_sync(FULLMASK, a, off);
            b += __shfl_xor_sync(FULLMASK, b, off);
            c += __shfl_xor_sync(FULLMASK, c, off);
        }
        if (lane == 0) {
            atomicAdd(&g_acc[0], (double)a);
            atomicAdd(&g_acc[1], (double)b);
            atomicAdd(&g_acc[2], (double)c);
        }
    }
}

__global__ void hat_fin_kernel(float* out, int E_pos, int E_neg, int out_size) {
    double loss = g_acc[0] / (double)E_pos + g_acc[1] / (double)E_neg;
    out[0] = (float)loss;
    if (out_size > 1) out[1] = (float)(g_acc[2] / (double)E_pos);
}

extern "C" void kernel_launch(void* const* d_in, const int* in_sizes, int n_in,
                              void* d_out, int out_size) {
    const float* h  = (const float*)d_in[0];
    const int*   ps = (const int*)d_in[1];
    const int*   pd = (const int*)d_in[2];
    const int*   ns = (const int*)d_in[3];
    const int*   nd = (const int*)d_in[4];

    const int E_pos = in_sizes[1];
    const int E_neg = in_sizes[3];
    const int nn    = (E_pos > 0) ? (E_neg / E_pos) : 1;
    const int N     = in_sizes[0] / 64;   // D = 64 (fixed by dataset)

    if (nn == 5 && N <= H16_CAP) {
        int p_threads = N * 16;
        hat_prep_kernel<<<(p_threads + 255) / 256, 256>>>(h, N);
        const int pairs = (E_pos + 1) / 2;
        int blocks = 1184;
        int max_blocks = (pairs + 7) / 8;           // >= 1 pair per warp
        if (blocks > max_blocks) blocks = max_blocks;
        hat_main5_kernel<<<blocks, 256>>>(ps, pd, ns, nd,
                                          E_pos, E_neg, (float*)d_out, out_size);
    } else {
        hat_init_kernel<<<1, 1>>>();
        const int gpb = 256 / 32;
        hat_generic_kernel<<<(E_pos + gpb - 1) / gpb, 256>>>(h, ps, pd, ns, nd, E_pos, nn);
        hat_fin_kernel<<<1, 1>>>((float*)d_out, E_pos, E_neg, out_size);
    }
}

// round 9
// speedup vs baseline: 2.8819x; 1.1257x over previous
#include <cuda_runtime.h>
#include <cuda_fp16.h>
#include <cstdint>

#define HAT_EPS   1e-5f
#define H16_CAP   524288      // fp16 fast-path node cap (64 MB static, L2-resident)
#define FULLMASK  0xffffffffu

// accumulators: [0]=sum softplus(pos), [1]=sum softplus(-neg), [2]=sum 1/(rank+1)
static __device__ double g_acc[3];            // zero-initialized at module load
static __device__ unsigned int g_done;        // ticket, reset by last block
static __device__ float  g_ia[H16_CAP];       // 1/max(1-||h_i||^2, eps) (fp32, exact)
static __device__ __half g_h16[(size_t)H16_CAP * 64];  // fp16 copy of h

__device__ __forceinline__ float hat_softplus(float x) {
    if (x > 30.0f) return x;
    return __logf(1.0f + __expf(x));
}

// ---------------------------------------------------------------------------
// Prepass: per node, ia = 1/max(1-||h||^2, eps) from fp32, fp16 row copy out.
// ---------------------------------------------------------------------------
__global__ void __launch_bounds__(256) hat_prep_kernel(const float* __restrict__ h, int N) {
    int tid  = blockIdx.x * blockDim.x + threadIdx.x;
    int node = tid >> 4;
    int sub  = tid & 15;
    if (node >= N) return;
    float4 a = __ldg((const float4*)(h + (size_t)node * 64) + sub);

    half2 lo = __float22half2_rn(make_float2(a.x, a.y));
    half2 hi = __float22half2_rn(make_float2(a.z, a.w));
    uint2 pack;
    pack.x = *(unsigned*)&lo;
    pack.y = *(unsigned*)&hi;
    *((uint2*)(g_h16 + (size_t)node * 64) + sub) = pack;

    float s = fmaf(a.x, a.x, fmaf(a.y, a.y, fmaf(a.z, a.z, a.w * a.w)));
    s += __shfl_xor_sync(FULLMASK, s, 8);
    s += __shfl_xor_sync(FULLMASK, s, 4);
    s += __shfl_xor_sync(FULLMASK, s, 2);
    s += __shfl_xor_sync(FULLMASK, s, 1);
    if (sub == 0) g_ia[node] = 1.0f / fmaxf(1.0f - s, HAT_EPS);
}

// ---------------------------------------------------------------------------
// Quad index loader. Distance L (lane 0..23): group = L&3, slot = L>>2.
// Quad m covers groups 4m .. 4m+3. slot 0 -> pos edge, 1..5 -> neg slots.
// ---------------------------------------------------------------------------
__device__ __forceinline__ int load_quad_idx(
    int m, int Q, int E_pos, bool isIdx, int grp, int slot,
    const int* __restrict__ b0, const int* __restrict__ b5)
{
    if (m >= Q || !isIdx) return 0;
    int g = 4 * m + grp;
    if (g >= E_pos) return 0;
    return (slot == 0) ? __ldg(&b0[g]) : __ldg(&b5[g * 5 + slot - 1]);
}

// ---------------------------------------------------------------------------
// Main kernel, NN=5: persistent warps, FOUR groups (one quad) per iteration.
// 8-lane teams; round r loads the rows of distances r*4+q (q = team).
// Lane L (0..23) owns distance L end-to-end: its src/dst indices, both ia
// values (no ib shuffle), and its score. Squares accumulate via half2 FMA
// (depth 2) then finish in fp32.
// ---------------------------------------------------------------------------
__global__ void __launch_bounds__(256, 4) hat_main5_kernel(
    const int* __restrict__ ps, const int* __restrict__ pd,
    const int* __restrict__ ns, const int* __restrict__ nd,
    int E_pos, int E_neg, float* __restrict__ out, int out_size)
{
    const int lane  = threadIdx.x & 31;
    const int wid   = threadIdx.x >> 5;
    const int tlane = lane & 7;           // lane within 8-lane team
    const int q     = lane >> 3;          // team id 0..3
    const int warp_global = blockIdx.x * (blockDim.x >> 5) + wid;
    const int total_warps = gridDim.x * (blockDim.x >> 5);
    const int Q = (E_pos + 3) >> 2;       // number of quads

    // ---- hoisted lane-role constants ----
    const bool isIdx = (lane < 24);
    const int  grp   = lane & 3;          // group within quad
    const int  slot  = lane >> 2;         // 0 = pos, 1..5 = neg (lanes < 24)
    const unsigned cntMask = 0x111110u << lane;   // valid on lanes 0..3

    float acc_pos = 0.0f, acc_neg = 0.0f, acc_rr = 0.0f;   // lanes 0..3

    int m    = warp_global;
    int idxS = load_quad_idx(m, Q, E_pos, isIdx, grp, slot, ps, ns);
    int idxD = load_quad_idx(m, Q, E_pos, isIdx, grp, slot, pd, nd);

    while (m < Q) {
        // both ia gathers are LOCAL to the owning lane (no shuffle later)
        float iaS = isIdx ? __ldg(&g_ia[idxS]) : 0.0f;
        float iaD = isIdx ? __ldg(&g_ia[idxD]) : 0.0f;

        float sq[6];

        // ---- wave 1: rounds 0..2 (teams x rounds -> distances r*4+q) ----
        uint4 ra[3], rb[3];
        #pragma unroll
        for (int r = 0; r < 3; r++) {
            int sl = (r << 2) + q;        // lane owning this distance's indices
            int s = __shfl_sync(FULLMASK, idxS, sl);
            int d = __shfl_sync(FULLMASK, idxD, sl);
            ra[r] = __ldg((const uint4*)(g_h16 + (size_t)s * 64) + tlane);
            rb[r] = __ldg((const uint4*)(g_h16 + (size_t)d * 64) + tlane);
        }

        // ---- prefetch next quad's indices while wave-1 rows are in flight ----
        const int mn = m + total_warps;
        int idxS2 = load_quad_idx(mn, Q, E_pos, isIdx, grp, slot, ps, ns);
        int idxD2 = load_quad_idx(mn, Q, E_pos, isIdx, grp, slot, pd, nd);

        #pragma unroll
        for (int r = 0; r < 3; r++) {
            half2 d0 = __hsub2(*(half2*)&ra[r].x, *(half2*)&rb[r].x);
            half2 d1 = __hsub2(*(half2*)&ra[r].y, *(half2*)&rb[r].y);
            half2 d2 = __hsub2(*(half2*)&ra[r].z, *(half2*)&rb[r].z);
            half2 d3 = __hsub2(*(half2*)&ra[r].w, *(half2*)&rb[r].w);
            half2 p  = __hfma2(d1, d1, __hmul2(d0, d0));
            half2 pq = __hfma2(d3, d3, __hmul2(d2, d2));
            float2 pf = __half22float2(p);
            float2 qf = __half22float2(pq);
            float s = (pf.x + pf.y) + (qf.x + qf.y);
            s += __shfl_xor_sync(FULLMASK, s, 1);
            s += __shfl_xor_sync(FULLMASK, s, 2);
            s += __shfl_xor_sync(FULLMASK, s, 4);
            sq[r] = s;
        }

        // ---- wave 2: rounds 3..5 ----
        #pragma unroll
        for (int r = 0; r < 3; r++) {
            int sl = ((r + 3) << 2) + q;
            int s = __shfl_sync(FULLMASK, idxS, sl);
            int d = __shfl_sync(FULLMASK, idxD, sl);
            ra[r] = __ldg((const uint4*)(g_h16 + (size_t)s * 64) + tlane);
            rb[r] = __ldg((const uint4*)(g_h16 + (size_t)d * 64) + tlane);
        }
        #pragma unroll
        for (int r = 0; r < 3; r++) {
            half2 d0 = __hsub2(*(half2*)&ra[r].x, *(half2*)&rb[r].x);
            half2 d1 = __hsub2(*(half2*)&ra[r].y, *(half2*)&rb[r].y);
            half2 d2 = __hsub2(*(half2*)&ra[r].z, *(half2*)&rb[r].z);
            half2 d3 = __hsub2(*(half2*)&ra[r].w, *(half2*)&rb[r].w);
            half2 p  = __hfma2(d1, d1, __hmul2(d0, d0));
            half2 pq = __hfma2(d3, d3, __hmul2(d2, d2));
            float2 pf = __half22float2(p);
            float2 qf = __half22float2(pq);
            float s = (pf.x + pf.y) + (qf.x + qf.y);
            s += __shfl_xor_sync(FULLMASK, s, 1);
            s += __shfl_xor_sync(FULLMASK, s, 2);
            s += __shfl_xor_sync(FULLMASK, s, 4);
            sq[r + 3] = s;
        }

        // ---- route: lane L pulls sq of distance L (round = slot, team = grp) ----
        float x0 = __shfl_sync(FULLMASK, sq[0], grp << 3);
        float x1 = __shfl_sync(FULLMASK, sq[1], grp << 3);
        float x2 = __shfl_sync(FULLMASK, sq[2], grp << 3);
        float x3 = __shfl_sync(FULLMASK, sq[3], grp << 3);
        float x4 = __shfl_sync(FULLMASK, sq[4], grp << 3);
        float x5 = __shfl_sync(FULLMASK, sq[5], grp << 3);
        float sv = (slot == 0) ? x0 : (slot == 1) ? x1 : (slot == 2) ? x2
                 : (slot == 3) ? x3 : (slot == 4) ? x4 : x5;

        float pr = iaS * iaD;   // both local — no shuffle

        // ---- one score pass for all 24 distances ----
        float gam = fmaxf(fmaf(2.0f * sv, pr, 1.0f), 1.0f + HAT_EPS);
        float d   = __logf(gam + __fsqrt_rn(fmaf(gam, gam, -1.0f)));
        float scv = d * d;

        float pos = __shfl_sync(FULLMASK, scv, grp);        // pos lanes are 0..3
        unsigned ball = __ballot_sync(FULLMASK, scv < pos); // -ns > -ps <=> ns < ps

        float arg = (lane < 4) ? scv : -scv;
        float sp  = hat_softplus(arg);
        float vneg = (lane >= 4 && lane < 24) ? sp : 0.0f;
        // xor-4/8/16 butterfly sums lanes with equal lane&3 (per-group sums)
        vneg += __shfl_xor_sync(FULLMASK, vneg, 4);
        vneg += __shfl_xor_sync(FULLMASK, vneg, 8);
        vneg += __shfl_xor_sync(FULLMASK, vneg, 16);

        if (lane < 4 && (4 * m + lane) < E_pos) {
            acc_pos += sp;
            acc_neg += vneg;
            acc_rr  += 1.0f / (float)(__popc(ball & cntMask) + 1);
        }

        m    = mn;
        idxS = idxS2;
        idxD = idxD2;
    }

    // fold lanes 1..3 into lane 0
    acc_pos += __shfl_xor_sync(FULLMASK, acc_pos, 1);
    acc_neg += __shfl_xor_sync(FULLMASK, acc_neg, 1);
    acc_rr  += __shfl_xor_sync(FULLMASK, acc_rr, 1);
    acc_pos += __shfl_xor_sync(FULLMASK, acc_pos, 2);
    acc_neg += __shfl_xor_sync(FULLMASK, acc_neg, 2);
    acc_rr  += __shfl_xor_sync(FULLMASK, acc_rr, 2);

    // ---- once per block: reduce -> global double atomics ----
    __shared__ float s_a[8], s_b[8], s_c[8];
    __shared__ bool  s_last;
    if (lane == 0) { s_a[wid] = acc_pos; s_b[wid] = acc_neg; s_c[wid] = acc_rr; }
    __syncthreads();
    if (wid == 0) {
        const int nw = blockDim.x >> 5;
        float va = (lane < nw) ? s_a[lane] : 0.0f;
        float vb = (lane < nw) ? s_b[lane] : 0.0f;
        float vc = (lane < nw) ? s_c[lane] : 0.0f;
        #pragma unroll
        for (int off = 4; off >= 1; off >>= 1) {
            va += __shfl_xor_sync(FULLMASK, va, off);
            vb += __shfl_xor_sync(FULLMASK, vb, off);
            vc += __shfl_xor_sync(FULLMASK, vc, off);
        }
        if (lane == 0) {
            atomicAdd(&g_acc[0], (double)va);
            atomicAdd(&g_acc[1], (double)vb);
            atomicAdd(&g_acc[2], (double)vc);
            __threadfence();
            unsigned ticket = atomicAdd(&g_done, 1u);
            s_last = (ticket == gridDim.x - 1);
        }
    }
    __syncthreads();

    // ---- last block finalizes and resets state for the next graph replay ----
    if (s_last && threadIdx.x == 0) {
        volatile double* acc = (volatile double*)g_acc;
        double a = acc[0], b = acc[1], c = acc[2];
        out[0] = (float)(a / (double)E_pos + b / (double)E_neg);
        if (out_size > 1) out[1] = (float)(c / (double)E_pos);
        g_acc[0] = 0.0; g_acc[1] = 0.0; g_acc[2] = 0.0;
        g_done = 0u;
        __threadfence();
    }
}

// ---------------------------------------------------------------------------
// Generic fallback (any nn or N > H16_CAP), fp32, self-contained.
// ---------------------------------------------------------------------------
__global__ void hat_init_kernel() {
    g_acc[0] = 0.0; g_acc[1] = 0.0; g_acc[2] = 0.0;
}

__global__ void __launch_bounds__(256) hat_generic_kernel(
    const float* __restrict__ h,
    const int* __restrict__ ps, const int* __restrict__ pd,
    const int* __restrict__ ns, const int* __restrict__ nd,
    int E_pos, int nn)
{
    const int lane = threadIdx.x & 31;
    const int wid  = threadIdx.x >> 5;
    const int g    = blockIdx.x * (blockDim.x >> 5) + wid;

    float sp_pos = 0.0f, sp_neg = 0.0f, inv_rank = 0.0f;

    if (g < E_pos) {
        float pos = 0.0f;
        int   cnt = 0;
        for (int t = 0; t <= nn; t++) {
            int src, dst;
            if (t == 0) { src = ps[g]; dst = pd[g]; }
            else {
                size_t e = (size_t)g * nn + (t - 1);
                src = ns[e]; dst = nd[e];
            }
            const float2* up = (const float2*)(h + (size_t)src * 64);
            const float2* vp = (const float2*)(h + (size_t)dst * 64);
            float2 a = up[lane], b = vp[lane];
            float dx = a.x - b.x, dy = a.y - b.y;
            float sq = dx * dx + dy * dy;
            float uu = a.x * a.x + a.y * a.y;
            float vv = b.x * b.x + b.y * b.y;
            #pragma unroll
            for (int off = 16; off >= 1; off >>= 1) {
                sq += __shfl_xor_sync(FULLMASK, sq, off);
                uu += __shfl_xor_sync(FULLMASK, uu, off);
                vv += __shfl_xor_sync(FULLMASK, vv, off);
            }
            if (lane == 0) {
                float alpha = fmaxf(1.0f - uu, HAT_EPS);
                float beta  = fmaxf(1.0f - vv, HAT_EPS);
                float gam   = fmaxf(1.0f + 2.0f * sq / (alpha * beta), 1.0f + HAT_EPS);
                float dd    = __logf(gam + __fsqrt_rn(fmaf(gam, gam, -1.0f)));
                float scv   = dd * dd;
                if (t == 0) { pos = scv; sp_pos = hat_softplus(scv); }
                else {
                    sp_neg += hat_softplus(-scv);
                    cnt += (scv < pos) ? 1 : 0;
                }
            }
        }
        if (lane == 0) inv_rank = 1.0f / (float)(cnt + 1);
    }

    __shared__ float s_a[8], s_b[8], s_c[8];
    if (lane == 0) { s_a[wid] = sp_pos; s_b[wid] = sp_neg; s_c[wid] = inv_rank; }
    __syncthreads();
    if (wid == 0) {
        const int nw = blockDim.x >> 5;
        float a = (lane < nw) ? s_a[lane] : 0.0f;
        float b = (lane < nw) ? s_b[lane] : 0.0f;
        float c = (lane < nw) ? s_c[lane] : 0.0f;
        #pragma unroll
        for (int off = 4; off >= 1; off >>= 1) {
            a += __shfl_xor_sync(FULLMASK, a, off);
            b += __shfl_xor_sync(FULLMASK, b, off);
            c += __shfl_xor_sync(FULLMASK, c, off);
        }
        if (lane == 0) {
            atomicAdd(&g_acc[0], (double)a);
            atomicAdd(&g_acc[1], (double)b);
            atomicAdd(&g_acc[2], (double)c);
        }
    }
}

__global__ void hat_fin_kernel(float* out, int E_pos, int E_neg, int out_size) {
    double loss = g_acc[0] / (double)E_pos + g_acc[1] / (double)E_neg;
    out[0] = (float)loss;
    if (out_size > 1) out[1] = (float)(g_acc[2] / (double)E_pos);
}

extern "C" void kernel_launch(void* const* d_in, const int* in_sizes, int n_in,
                              void* d_out, int out_size) {
    const float* h  = (const float*)d_in[0];
    const int*   ps = (const int*)d_in[1];
    const int*   pd = (const int*)d_in[2];
    const int*   ns = (const int*)d_in[3];
    const int*   nd = (const int*)d_in[4];

    const int E_pos = in_sizes[1];
    const int E_neg = in_sizes[3];
    const int nn    = (E_pos > 0) ? (E_neg / E_pos) : 1;
    const int N     = in_sizes[0] / 64;   // D = 64 (fixed by dataset)

    if (nn == 5 && N <= H16_CAP) {
        int p_threads = N * 16;
        hat_prep_kernel<<<(p_threads + 255) / 256, 256>>>(h, N);
        const int quads = (E_pos + 3) / 4;
        int blocks = 1184;
        int max_blocks = (quads + 7) / 8;           // >= 1 quad per warp
        if (blocks > max_blocks) blocks = max_blocks;
        hat_main5_kernel<<<blocks, 256>>>(ps, pd, ns, nd,
                                          E_pos, E_neg, (float*)d_out, out_size);
    } else {
        hat_init_kernel<<<1, 1>>>();
        const int gpb = 256 / 32;
        hat_generic_kernel<<<(E_pos + gpb - 1) / gpb, 256>>>(h, ps, pd, ns, nd, E_pos, nn);
        hat_fin_kernel<<<1, 1>>>((float*)d_out, E_pos, E_neg, out_size);
    }
}

// round 11
// speedup vs baseline: 2.8934x; 1.0040x over previous
#include <cuda_runtime.h>
#include <cuda_fp16.h>
#include <cstdint>

#define HAT_EPS   1e-5f
#define H16_CAP   524288      // fp16 fast-path node cap (64 MB static, L2-resident)
#define FULLMASK  0xffffffffu

// accumulators: [0]=sum softplus(pos), [1]=sum softplus(-neg), [2]=sum 1/(rank+1)
static __device__ double g_acc[3];            // zero-initialized at module load
static __device__ unsigned int g_done;        // ticket, reset by last block
static __device__ float  g_ia[H16_CAP];       // 1/max(1-||h_i||^2, eps) (fp32, exact)
static __device__ __half g_h16[(size_t)H16_CAP * 64];  // fp16 copy of h

__device__ __forceinline__ float hat_softplus(float x) {
    if (x > 30.0f) return x;
    return __logf(1.0f + __expf(x));
}

// ---------------------------------------------------------------------------
// Prepass: per node, ia = 1/max(1-||h||^2, eps) from fp32, fp16 row copy out.
// ---------------------------------------------------------------------------
__global__ void __launch_bounds__(256) hat_prep_kernel(const float* __restrict__ h, int N) {
    int tid  = blockIdx.x * blockDim.x + threadIdx.x;
    int node = tid >> 4;
    int sub  = tid & 15;
    if (node >= N) return;
    float4 a = __ldg((const float4*)(h + (size_t)node * 64) + sub);

    half2 lo = __float22half2_rn(make_float2(a.x, a.y));
    half2 hi = __float22half2_rn(make_float2(a.z, a.w));
    uint2 pack;
    pack.x = *(unsigned*)&lo;
    pack.y = *(unsigned*)&hi;
    *((uint2*)(g_h16 + (size_t)node * 64) + sub) = pack;

    float s = fmaf(a.x, a.x, fmaf(a.y, a.y, fmaf(a.z, a.z, a.w * a.w)));
    s += __shfl_xor_sync(FULLMASK, s, 8);
    s += __shfl_xor_sync(FULLMASK, s, 4);
    s += __shfl_xor_sync(FULLMASK, s, 2);
    s += __shfl_xor_sync(FULLMASK, s, 1);
    if (sub == 0) g_ia[node] = 1.0f / fmaxf(1.0f - s, HAT_EPS);
}

// ---------------------------------------------------------------------------
// Quad index loader (owner-lane mapping): lane 8q+r owns distance slot r of
// group 4m+q. slot 0 -> pos edge, slots 1..5 -> neg edges.
// ---------------------------------------------------------------------------
__device__ __forceinline__ int load_quad_idx(
    int m, int Q, int E_pos, bool owner, int grp, int slot,
    const int* __restrict__ b0, const int* __restrict__ b5)
{
    if (m >= Q || !owner) return 0;
    int g = 4 * m + grp;
    if (g >= E_pos) return 0;
    return (slot == 0) ? __ldg(&b0[g]) : __ldg(&b5[g * 5 + slot - 1]);
}

// ---------------------------------------------------------------------------
// Main kernel, NN=5: persistent warps, FOUR groups (one quad) per iteration.
// Team q (8 lanes) owns group 4m+q end-to-end: round r loads/reduces the rows
// of its slot-r distance; owner lane 8q+r captures sq locally (no routing
// shuffles), already holds both indices and both ia values, and scores its
// distance. Ballot/softplus/rank all team-local.
// ---------------------------------------------------------------------------
__global__ void __launch_bounds__(256, 5) hat_main5_kernel(
    const int* __restrict__ ps, const int* __restrict__ pd,
    const int* __restrict__ ns, const int* __restrict__ nd,
    int E_pos, int E_neg, float* __restrict__ out, int out_size)
{
    const int lane  = threadIdx.x & 31;
    const int wid   = threadIdx.x >> 5;
    const int tlane = lane & 7;           // slot owned (0..5 active)
    const int q     = lane >> 3;          // team id = group within quad
    const int tbase = lane & ~7;          // team's lane 0
    const int warp_global = blockIdx.x * (blockDim.x >> 5) + wid;
    const int total_warps = gridDim.x * (blockDim.x >> 5);
    const int Q = (E_pos + 3) >> 2;       // number of quads

    const bool owner = (tlane < 6);
    const unsigned cntMask = 0x3Eu << tbase;   // team's neg lanes (for leader)

    float acc_pos = 0.0f, acc_neg = 0.0f, acc_rr = 0.0f;   // team leaders

    int m    = warp_global;
    int idxS = load_quad_idx(m, Q, E_pos, owner, q, tlane, ps, ns);
    int idxD = load_quad_idx(m, Q, E_pos, owner, q, tlane, pd, nd);

    while (m < Q) {
        // both ia gathers local to the owning lane
        float iaS = owner ? __ldg(&g_ia[idxS]) : 0.0f;
        float iaD = owner ? __ldg(&g_ia[idxD]) : 0.0f;

        float sv = 0.0f;

        // ---- wave 1: slots 0..2 of this team's group ----
        uint4 ra[3], rb[3];
        #pragma unroll
        for (int r = 0; r < 3; r++) {
            int s = __shfl_sync(FULLMASK, idxS, tbase + r);
            int d = __shfl_sync(FULLMASK, idxD, tbase + r);
            ra[r] = __ldg((const uint4*)(g_h16 + (size_t)s * 64) + tlane);
            rb[r] = __ldg((const uint4*)(g_h16 + (size_t)d * 64) + tlane);
        }

        // ---- prefetch next quad's indices while wave-1 rows are in flight ----
        const int mn = m + total_warps;
        int idxS2 = load_quad_idx(mn, Q, E_pos, owner, q, tlane, ps, ns);
        int idxD2 = load_quad_idx(mn, Q, E_pos, owner, q, tlane, pd, nd);

        #pragma unroll
        for (int r = 0; r < 3; r++) {
            half2 d0 = __hsub2(*(half2*)&ra[r].x, *(half2*)&rb[r].x);
            half2 d1 = __hsub2(*(half2*)&ra[r].y, *(half2*)&rb[r].y);
            half2 d2 = __hsub2(*(half2*)&ra[r].z, *(half2*)&rb[r].z);
            half2 d3 = __hsub2(*(half2*)&ra[r].w, *(half2*)&rb[r].w);
            half2 p  = __hfma2(d1, d1, __hmul2(d0, d0));
            half2 pq = __hfma2(d3, d3, __hmul2(d2, d2));
            float2 pf = __half22float2(p);
            float2 qf = __half22float2(pq);
            float s = (pf.x + pf.y) + (qf.x + qf.y);
            s += __shfl_xor_sync(FULLMASK, s, 1);
            s += __shfl_xor_sync(FULLMASK, s, 2);
            s += __shfl_xor_sync(FULLMASK, s, 4);
            if (tlane == r) sv = s;      // owner captures — no routing shuffles
        }

        // ---- wave 2: slots 3..5 ----
        #pragma unroll
        for (int r = 0; r < 3; r++) {
            int s = __shfl_sync(FULLMASK, idxS, tbase + r + 3);
            int d = __shfl_sync(FULLMASK, idxD, tbase + r + 3);
            ra[r] = __ldg((const uint4*)(g_h16 + (size_t)s * 64) + tlane);
            rb[r] = __ldg((const uint4*)(g_h16 + (size_t)d * 64) + tlane);
        }
        #pragma unroll
        for (int r = 0; r < 3; r++) {
            half2 d0 = __hsub2(*(half2*)&ra[r].x, *(half2*)&rb[r].x);
            half2 d1 = __hsub2(*(half2*)&ra[r].y, *(half2*)&rb[r].y);
            half2 d2 = __hsub2(*(half2*)&ra[r].z, *(half2*)&rb[r].z);
            half2 d3 = __hsub2(*(half2*)&ra[r].w, *(half2*)&rb[r].w);
            half2 p  = __hfma2(d1, d1, __hmul2(d0, d0));
            half2 pq = __hfma2(d3, d3, __hmul2(d2, d2));
            float2 pf = __half22float2(p);
            float2 qf = __half22float2(pq);
            float s = (pf.x + pf.y) + (qf.x + qf.y);
            s += __shfl_xor_sync(FULLMASK, s, 1);
            s += __shfl_xor_sync(FULLMASK, s, 2);
            s += __shfl_xor_sync(FULLMASK, s, 4);
            if (tlane == r + 3) sv = s;
        }

        float pr = iaS * iaD;   // both local — no shuffle

        // ---- one score pass; each owner lane scores its own distance ----
        float gam = fmaxf(fmaf(2.0f * sv, pr, 1.0f), 1.0f + HAT_EPS);
        float d   = __logf(gam + __fsqrt_rn(fmaf(gam, gam, -1.0f)));
        float scv = d * d;

        float pos = __shfl_sync(FULLMASK, scv, tbase);      // team's slot-0 lane
        unsigned ball = __ballot_sync(FULLMASK, scv < pos); // -ns > -ps <=> ns < ps

        float arg = (tlane == 0) ? scv : -scv;
        float sp  = hat_softplus(arg);
        float vneg = (tlane >= 1 && tlane < 6) ? sp : 0.0f;
        vneg += __shfl_xor_sync(FULLMASK, vneg, 1);          // team-local butterfly
        vneg += __shfl_xor_sync(FULLMASK, vneg, 2);
        vneg += __shfl_xor_sync(FULLMASK, vneg, 4);

        if (tlane == 0 && (4 * m + q) < E_pos) {
            acc_pos += sp;
            acc_neg += vneg;
            acc_rr  += 1.0f / (float)(__popc(ball & cntMask) + 1);
        }

        m    = mn;
        idxS = idxS2;
        idxD = idxD2;
    }

    // fold team leaders (lanes 0,8,16,24) into lane 0
    acc_pos += __shfl_xor_sync(FULLMASK, acc_pos, 8);
    acc_neg += __shfl_xor_sync(FULLMASK, acc_neg, 8);
    acc_rr  += __shfl_xor_sync(FULLMASK, acc_rr, 8);
    acc_pos += __shfl_xor_sync(FULLMASK, acc_pos, 16);
    acc_neg += __shfl_xor_sync(FULLMASK, acc_neg, 16);
    acc_rr  += __shfl_xor_sync(FULLMASK, acc_rr, 16);

    // ---- once per block: reduce -> global double atomics ----
    __shared__ float s_a[8], s_b[8], s_c[8];
    __shared__ bool  s_last;
    if (lane == 0) { s_a[wid] = acc_pos; s_b[wid] = acc_neg; s_c[wid] = acc_rr; }
    __syncthreads();
    if (wid == 0) {
        const int nw = blockDim.x >> 5;
        float va = (lane < nw) ? s_a[lane] : 0.0f;
        float vb = (lane < nw) ? s_b[lane] : 0.0f;
        float vc = (lane < nw) ? s_c[lane] : 0.0f;
        #pragma unroll
        for (int off = 4; off >= 1; off >>= 1) {
            va += __shfl_xor_sync(FULLMASK, va, off);
            vb += __shfl_xor_sync(FULLMASK, vb, off);
            vc += __shfl_xor_sync(FULLMASK, vc, off);
        }
        if (lane == 0) {
            atomicAdd(&g_acc[0], (double)va);
            atomicAdd(&g_acc[1], (double)vb);
            atomicAdd(&g_acc[2], (double)vc);
            __threadfence();
            unsigned ticket = atomicAdd(&g_done, 1u);
            s_last = (ticket == gridDim.x - 1);
        }
    }
    __syncthreads();

    // ---- last block finalizes and resets state for the next graph replay ----
    if (s_last && threadIdx.x == 0) {
        volatile double* acc = (volatile double*)g_acc;
        double a = acc[0], b = acc[1], c = acc[2];
        out[0] = (float)(a / (double)E_pos + b / (double)E_neg);
        if (out_size > 1) out[1] = (float)(c / (double)E_pos);
        g_acc[0] = 0.0; g_acc[1] = 0.0; g_acc[2] = 0.0;
        g_done = 0u;
        __threadfence();
    }
}

// ---------------------------------------------------------------------------
// Generic fallback (any nn or N > H16_CAP), fp32, self-contained.
// ---------------------------------------------------------------------------
__global__ void hat_init_kernel() {
    g_acc[0] = 0.0; g_acc[1] = 0.0; g_acc[2] = 0.0;
}

__global__ void __launch_bounds__(256) hat_generic_kernel(
    const float* __restrict__ h,
    const int* __restrict__ ps, const int* __restrict__ pd,
    const int* __restrict__ ns, const int* __restrict__ nd,
    int E_pos, int nn)
{
    const int lane = threadIdx.x & 31;
    const int wid  = threadIdx.x >> 5;
    const int g    = blockIdx.x * (blockDim.x >> 5) + wid;

    float sp_pos = 0.0f, sp_neg = 0.0f, inv_rank = 0.0f;

    if (g < E_pos) {
        float pos = 0.0f;
        int   cnt = 0;
        for (int t = 0; t <= nn; t++) {
            int src, dst;
            if (t == 0) { src = ps[g]; dst = pd[g]; }
            else {
                size_t e = (size_t)g * nn + (t - 1);
                src = ns[e]; dst = nd[e];
            }
            const float2* up = (const float2*)(h + (size_t)src * 64);
            const float2* vp = (const float2*)(h + (size_t)dst * 64);
            float2 a = up[lane], b = vp[lane];
            float dx = a.x - b.x, dy = a.y - b.y;
            float sq = dx * dx + dy * dy;
            float uu = a.x * a.x + a.y * a.y;
            float vv = b.x * b.x + b.y * b.y;
            #pragma unroll
            for (int off = 16; off >= 1; off >>= 1) {
                sq += __shfl_xor_sync(FULLMASK, sq, off);
                uu += __shfl_xor_sync(FULLMASK, uu, off);
                vv += __shfl_xor_sync(FULLMASK, vv, off);
            }
            if (lane == 0) {
                float alpha = fmaxf(1.0f - uu, HAT_EPS);
                float beta  = fmaxf(1.0f - vv, HAT_EPS);
                float gam   = fmaxf(1.0f + 2.0f * sq / (alpha * beta), 1.0f + HAT_EPS);
                float dd    = __logf(gam + __fsqrt_rn(fmaf(gam, gam, -1.0f)));
                float scv   = dd * dd;
                if (t == 0) { pos = scv; sp_pos = hat_softplus(scv); }
                else {
                    sp_neg += hat_softplus(-scv);
                    cnt += (scv < pos) ? 1 : 0;
                }
            }
        }
        if (lane == 0) inv_rank = 1.0f / (float)(cnt + 1);
    }

    __shared__ float s_a[8], s_b[8], s_c[8];
    if (lane == 0) { s_a[wid] = sp_pos; s_b[wid] = sp_neg; s_c[wid] = inv_rank; }
    __syncthreads();
    if (wid == 0) {
        const int nw = blockDim.x >> 5;
        float a = (lane < nw) ? s_a[lane] : 0.0f;
        float b = (lane < nw) ? s_b[lane] : 0.0f;
        float c = (lane < nw) ? s_c[lane] : 0.0f;
        #pragma unroll
        for (int off = 4; off >= 1; off >>= 1) {
            a += __shfl_xor_sync(FULLMASK, a, off);
            b += __shfl_xor_sync(FULLMASK, b, off);
            c += __shfl_xor_sync(FULLMASK, c, off);
        }
        if (lane == 0) {
            atomicAdd(&g_acc[0], (double)a);
            atomicAdd(&g_acc[1], (double)b);
            atomicAdd(&g_acc[2], (double)c);
        }
    }
}

__global__ void hat_fin_kernel(float* out, int E_pos, int E_neg, int out_size) {
    double loss = g_acc[0] / (double)E_pos + g_acc[1] / (double)E_neg;
    out[0] = (float)loss;
    if (out_size > 1) out[1] = (float)(g_acc[2] / (double)E_pos);
}

extern "C" void kernel_launch(void* const* d_in, const int* in_sizes, int n_in,
                              void* d_out, int out_size) {
    const float* h  = (const float*)d_in[0];
    const int*   ps = (const int*)d_in[1];
    const int*   pd = (const int*)d_in[2];
    const int*   ns = (const int*)d_in[3];
    const int*   nd = (const int*)d_in[4];

    const int E_pos = in_sizes[1];
    const int E_neg = in_sizes[3];
    const int nn    = (E_pos > 0) ? (E_neg / E_pos) : 1;
    const int N     = in_sizes[0] / 64;   // D = 64 (fixed by dataset)

    if (nn == 5 && N <= H16_CAP) {
        int p_threads = N * 16;
        hat_prep_kernel<<<(p_threads + 255) / 256, 256>>>(h, N);
        const int quads = (E_pos + 3) / 4;
        int blocks = 740;                            // 5 blocks/SM x 148 SMs
        int max_blocks = (quads + 7) / 8;            // >= 1 quad per warp
        if (blocks > max_blocks) blocks = max_blocks;
        hat_main5_kernel<<<blocks, 256>>>(ps, pd, ns, nd,
                                          E_pos, E_neg, (float*)d_out, out_size);
    } else {
        hat_init_kernel<<<1, 1>>>();
        const int gpb = 256 / 32;
        hat_generic_kernel<<<(E_pos + gpb - 1) / gpb, 256>>>(h, ps, pd, ns, nd, E_pos, nn);
        hat_fin_kernel<<<1, 1>>>((float*)d_out, E_pos, E_neg, out_size);
    }
}